// round 4
// baseline (speedup 1.0000x reference)
#include <cuda_runtime.h>
#include <cuda_bf16.h>
#include <cstdint>
#include <cstdio>

// ---------------------------------------------------------------------------
// EAGLE draft layer forward, sm_103a. Round 2: TF32 GEMM with
//  - cvt-to-tf32 at smem store (out of inner loop)
//  - ldmatrix.x4 fragment loads (6 LDSM vs 48 LDS per K-tile)
//  - double-buffered smem with register-staged global loads
// ---------------------------------------------------------------------------

#define S_LEN 2048
#define H_DIM 4096
#define H2_DIM 8192
#define NHEADS 32
#define NKV 8
#define HEADD 128
#define KVDIM (NKV * HEADD)      // 1024
#define QDIM  (NHEADS * HEADD)   // 4096
#define I_DIM 11008

// ------------------------- static scratch (fp32) ---------------------------
__device__ float g_cat[(size_t)S_LEN * H2_DIM];
__device__ float g_x1 [(size_t)S_LEN * H_DIM];
__device__ float g_h1 [(size_t)S_LEN * H_DIM];
__device__ float g_qf [(size_t)S_LEN * QDIM];
__device__ float g_kf [(size_t)S_LEN * KVDIM];
__device__ float g_vf [(size_t)S_LEN * KVDIM];
__device__ float g_vt [(size_t)KVDIM * S_LEN];
__device__ float g_sc [(size_t)NHEADS * S_LEN * S_LEN];
__device__ float g_ao [(size_t)S_LEN * QDIM];
__device__ float g_x2 [(size_t)S_LEN * H_DIM];
__device__ float g_h2 [(size_t)S_LEN * H_DIM];
__device__ float g_gf [(size_t)S_LEN * I_DIM];
__device__ float g_uf [(size_t)S_LEN * I_DIM];

// --------------------------- elementwise kernels ---------------------------

__global__ void concat_kernel(const float* __restrict__ emb,
                              const float* __restrict__ hid,
                              float* __restrict__ cat) {
    int idx = blockIdx.x * 256 + threadIdx.x;
    int s = idx >> 13;
    int c = idx & 8191;
    cat[idx] = (c < H_DIM) ? emb[(size_t)s * H_DIM + c]
                           : hid[(size_t)s * H_DIM + (c - H_DIM)];
}

__global__ __launch_bounds__(256) void rmsnorm_kernel(const float* __restrict__ x,
                                                      const float* __restrict__ w,
                                                      float* __restrict__ out) {
    int row = blockIdx.x;
    const float* xr = x + (size_t)row * H_DIM;
    float s = 0.f;
    for (int i = threadIdx.x; i < H_DIM; i += 256) { float v = xr[i]; s += v * v; }
    __shared__ float red[256];
    red[threadIdx.x] = s; __syncthreads();
    #pragma unroll
    for (int k = 128; k > 0; k >>= 1) {
        if (threadIdx.x < k) red[threadIdx.x] += red[threadIdx.x + k];
        __syncthreads();
    }
    float scale = rsqrtf(red[0] / (float)H_DIM + 1e-6f);
    for (int i = threadIdx.x; i < H_DIM; i += 256)
        out[(size_t)row * H_DIM + i] = xr[i] * scale * w[i];
}

// In-place RoPE: one thread handles the (d, d+64) pair; pos = seq index.
__global__ void rope_kernel(float* __restrict__ buf, int nheads) {
    int idx = blockIdx.x * 256 + threadIdx.x;
    int total = S_LEN * nheads * 64;
    if (idx >= total) return;
    int i    = idx & 63;
    int head = (idx >> 6) % nheads;
    int s    = idx / (nheads * 64);
    float pos = (float)s;
    float inv = expf(-(float)(2 * i) * (9.210340371976184f / 128.f));
    float ang = pos * inv;
    float c = cosf(ang), sn = sinf(ang);
    size_t base = (size_t)s * (nheads * HEADD) + (size_t)head * HEADD + i;
    float x1 = buf[base], x2 = buf[base + 64];
    buf[base]      = x1 * c - x2 * sn;
    buf[base + 64] = x2 * c + x1 * sn;
}

__global__ void transpose_kernel(const float* __restrict__ in,
                                 float* __restrict__ out, int rows, int cols) {
    __shared__ float tile[32][33];
    int c0 = blockIdx.x * 32, r0 = blockIdx.y * 32;
    int x = threadIdx.x, y = threadIdx.y;
    #pragma unroll
    for (int j = 0; j < 32; j += 8)
        tile[y + j][x] = in[(size_t)(r0 + y + j) * cols + (c0 + x)];
    __syncthreads();
    #pragma unroll
    for (int j = 0; j < 32; j += 8)
        out[(size_t)(c0 + y + j) * rows + (r0 + x)] = tile[x][y + j];
}

__global__ __launch_bounds__(256) void softmax_kernel(float* __restrict__ sc,
                                                      const float* __restrict__ amask) {
    int i = blockIdx.x;
    int h = blockIdx.y;
    float* row = sc + ((size_t)h * S_LEN + i) * S_LEN;
    int t = threadIdx.x;
    float v[8];
    float mx = -INFINITY;
    #pragma unroll
    for (int r = 0; r < 8; r++) {
        int j = t + r * 256;
        bool ok = (j <= i) && (amask[j] > 0.5f);
        float x = ok ? row[j] : -INFINITY;
        v[r] = x;
        mx = fmaxf(mx, x);
    }
    __shared__ float red[256];
    red[t] = mx; __syncthreads();
    #pragma unroll
    for (int k = 128; k > 0; k >>= 1) {
        if (t < k) red[t] = fmaxf(red[t], red[t + k]);
        __syncthreads();
    }
    mx = red[0]; __syncthreads();
    float sum = 0.f;
    #pragma unroll
    for (int r = 0; r < 8; r++) { float e = expf(v[r] - mx); v[r] = e; sum += e; }
    red[t] = sum; __syncthreads();
    #pragma unroll
    for (int k = 128; k > 0; k >>= 1) {
        if (t < k) red[t] += red[t + k];
        __syncthreads();
    }
    float invs = 1.f / red[0];
    #pragma unroll
    for (int r = 0; r < 8; r++) row[t + r * 256] = v[r] * invs;
}

__global__ void silu_mul_kernel(float* __restrict__ g, const float* __restrict__ u,
                                size_t n) {
    size_t idx = (size_t)blockIdx.x * 256 + threadIdx.x;
    if (idx < n) {
        float x = g[idx];
        g[idx] = x * (1.f / (1.f + expf(-x))) * u[idx];
    }
}

// ----------------------------- TF32 NT GEMM --------------------------------
// C[M,N] = alpha * A[M,K] * B[N,K]^T (+ bias) (+ res). BM=BN=128, BK=16,
// 8 warps (2x4), warp tile 64x32, m16n8k8 TF32 mma.
// smem holds tf32 bit patterns (converted at store); fragments via ldmatrix;
// double-buffered smem, register-staged global loads.

#define ROWW 20                    // smem row width in words (80 B)
#define BUFW (128 * ROWW)          // words per buffer

__device__ __forceinline__ uint32_t f2tf(float x) {
    uint32_t r;
    asm("cvt.rna.tf32.f32 %0, %1;" : "=r"(r) : "f"(x));
    return r;
}

__global__ __launch_bounds__(256) void gemm_tf32_nt(
    const float* __restrict__ A, const float* __restrict__ B, float* __restrict__ C,
    int M, int N, int K, int lda, int ldb, int ldc, float alpha,
    const float* __restrict__ bias, const float* __restrict__ res, int ldres,
    long long aStride, int aDiv, long long bStride, int bDiv, long long cStride)
{
    (void)M; (void)N;
    __shared__ __align__(16) uint32_t As[2 * BUFW];
    __shared__ __align__(16) uint32_t Bs[2 * BUFW];

    int z = blockIdx.z;
    A += (long long)(z / aDiv) * aStride;
    B += (long long)(z / bDiv) * bStride;
    C += (long long)z * cStride;

    int tid  = threadIdx.x;
    int warp = tid >> 5, lane = tid & 31;
    int wm = warp >> 2;       // 0..1
    int wn = warp & 3;        // 0..3
    int bm = blockIdx.y * 128, bn = blockIdx.x * 128;
    int g = lane >> 2, ctg = lane & 3;

    float acc[4][4][4] = {};

    // global staging addressing
    int lrow = tid >> 2;            // 0..63
    int lcol = (tid & 3) * 4;       // 0,4,8,12
    const float* Aptr = A + (size_t)(bm + lrow) * lda + lcol;
    const float* Bptr = B + (size_t)(bn + lrow) * ldb + lcol;

    // smem store addressing (word index)
    int stIdx = lrow * ROWW + lcol;

    // ldmatrix per-lane addresses (bytes).
    // A (x4 per m-tile): lanes 0-7 rows 0-7 lo16B, 8-15 rows 8-15 lo, 16-23 rows 0-7 hi, 24-31 rows 8-15 hi
    uint32_t smA = (uint32_t)__cvta_generic_to_shared(As);
    uint32_t smB = (uint32_t)__cvta_generic_to_shared(Bs);
    uint32_t aAddr = smA + ((uint32_t)(wm * 64 + (lane & 15)) * (ROWW * 4))
                   + ((uint32_t)(lane >> 4) << 4);
    // B (x4 per pair of n-tiles): lanes 0-7 rows 0-7 lo, 8-15 rows 0-7 hi,
    //                             16-23 rows 8-15 lo, 24-31 rows 8-15 hi
    uint32_t bAddr = smB + ((uint32_t)(wn * 32 + (lane & 7) + ((lane >> 4) << 3)) * (ROWW * 4))
                   + ((uint32_t)((lane >> 3) & 1) << 4);

    float4 sa0, sa1, sb0, sb1;

    // prologue: stage tile 0
    sa0 = *(const float4*)(Aptr);
    sa1 = *(const float4*)(Aptr + (size_t)64 * lda);
    sb0 = *(const float4*)(Bptr);
    sb1 = *(const float4*)(Bptr + (size_t)64 * ldb);
    {
        uint4 u;
        u.x = f2tf(sa0.x); u.y = f2tf(sa0.y); u.z = f2tf(sa0.z); u.w = f2tf(sa0.w);
        *(uint4*)&As[stIdx] = u;
        u.x = f2tf(sa1.x); u.y = f2tf(sa1.y); u.z = f2tf(sa1.z); u.w = f2tf(sa1.w);
        *(uint4*)&As[stIdx + 64 * ROWW] = u;
        u.x = f2tf(sb0.x); u.y = f2tf(sb0.y); u.z = f2tf(sb0.z); u.w = f2tf(sb0.w);
        *(uint4*)&Bs[stIdx] = u;
        u.x = f2tf(sb1.x); u.y = f2tf(sb1.y); u.z = f2tf(sb1.z); u.w = f2tf(sb1.w);
        *(uint4*)&Bs[stIdx + 64 * ROWW] = u;
    }
    __syncthreads();

    int nIter = K >> 4;
    for (int it = 0; it < nIter; it++) {
        int buf = it & 1;
        bool more = (it + 1) < nIter;
        if (more) {
            int k0 = (it + 1) << 4;
            sa0 = *(const float4*)(Aptr + k0);
            sa1 = *(const float4*)(Aptr + (size_t)64 * lda + k0);
            sb0 = *(const float4*)(Bptr + k0);
            sb1 = *(const float4*)(Bptr + (size_t)64 * ldb + k0);
        }

        uint32_t bufB = (uint32_t)buf * (BUFW * 4);
        #pragma unroll
        for (int kk = 0; kk < 2; kk++) {
            uint32_t a[4][4], b[4][2];
            #pragma unroll
            for (int mt = 0; mt < 4; mt++) {
                uint32_t ad = aAddr + bufB + (uint32_t)(mt * 16 * ROWW * 4) + (uint32_t)(kk * 32);
                asm volatile("ldmatrix.sync.aligned.m8n8.x4.shared.b16 {%0,%1,%2,%3}, [%4];"
                             : "=r"(a[mt][0]), "=r"(a[mt][1]), "=r"(a[mt][2]), "=r"(a[mt][3])
                             : "r"(ad));
            }
            #pragma unroll
            for (int j = 0; j < 2; j++) {
                uint32_t bd = bAddr + bufB + (uint32_t)(j * 16 * ROWW * 4) + (uint32_t)(kk * 32);
                asm volatile("ldmatrix.sync.aligned.m8n8.x4.shared.b16 {%0,%1,%2,%3}, [%4];"
                             : "=r"(b[2*j][0]), "=r"(b[2*j][1]), "=r"(b[2*j+1][0]), "=r"(b[2*j+1][1])
                             : "r"(bd));
            }
            #pragma unroll
            for (int mt = 0; mt < 4; mt++)
                #pragma unroll
                for (int nt = 0; nt < 4; nt++)
                    asm volatile(
                        "mma.sync.aligned.m16n8k8.row.col.f32.tf32.tf32.f32 "
                        "{%0,%1,%2,%3}, {%4,%5,%6,%7}, {%8,%9}, {%0,%1,%2,%3};"
                        : "+f"(acc[mt][nt][0]), "+f"(acc[mt][nt][1]),
                          "+f"(acc[mt][nt][2]), "+f"(acc[mt][nt][3])
                        : "r"(a[mt][0]), "r"(a[mt][1]), "r"(a[mt][2]), "r"(a[mt][3]),
                          "r"(b[nt][0]), "r"(b[nt][1]));
        }

        if (more) {
            int st = (buf ^ 1) * BUFW + stIdx;
            uint4 u;
            u.x = f2tf(sa0.x); u.y = f2tf(sa0.y); u.z = f2tf(sa0.z); u.w = f2tf(sa0.w);
            *(uint4*)&As[st] = u;
            u.x = f2tf(sa1.x); u.y = f2tf(sa1.y); u.z = f2tf(sa1.z); u.w = f2tf(sa1.w);
            *(uint4*)&As[st + 64 * ROWW] = u;
            u.x = f2tf(sb0.x); u.y = f2tf(sb0.y); u.z = f2tf(sb0.z); u.w = f2tf(sb0.w);
            *(uint4*)&Bs[st] = u;
            u.x = f2tf(sb1.x); u.y = f2tf(sb1.y); u.z = f2tf(sb1.z); u.w = f2tf(sb1.w);
            *(uint4*)&Bs[st + 64 * ROWW] = u;
        }
        __syncthreads();
    }

    // epilogue: float2 stores
    #pragma unroll
    for (int mt = 0; mt < 4; mt++) {
        int row0 = bm + wm * 64 + mt * 16 + g;
        #pragma unroll
        for (int nt = 0; nt < 4; nt++) {
            int col0 = bn + wn * 32 + nt * 8 + ctg * 2;
            #pragma unroll
            for (int half = 0; half < 2; half++) {
                int row = row0 + half * 8;
                float2 v;
                v.x = acc[mt][nt][half * 2 + 0] * alpha;
                v.y = acc[mt][nt][half * 2 + 1] * alpha;
                if (bias) { v.x += bias[col0]; v.y += bias[col0 + 1]; }
                if (res) {
                    const float2 r = *(const float2*)&res[(size_t)row * ldres + col0];
                    v.x += r.x; v.y += r.y;
                }
                *(float2*)&C[(size_t)row * ldc + col0] = v;
            }
        }
    }
}

static inline void run_gemm(const float* A, const float* B, float* C,
                            int M, int N, int K, int lda, int ldb, int ldc,
                            float alpha, const float* bias,
                            const float* res, int ldres,
                            long long aStride, int aDiv,
                            long long bStride, int bDiv,
                            long long cStride, int batch) {
    dim3 grid(N / 128, M / 128, batch);
    gemm_tf32_nt<<<grid, 256>>>(A, B, C, M, N, K, lda, ldb, ldc, alpha,
                                bias, res, ldres, aStride, aDiv, bStride, bDiv, cStride);
}

// ------------------------------ orchestration ------------------------------

extern "C" void kernel_launch(void* const* d_in, const int* in_sizes, int n_in,
                              void* d_out, int out_size) {
    (void)in_sizes; (void)n_in; (void)out_size;
    const float* hidden  = (const float*)d_in[0];
    const float* embeds  = (const float*)d_in[1];
    const float* amask   = (const float*)d_in[2];
    const float* fc_w    = (const float*)d_in[3];
    const float* fc_b    = (const float*)d_in[4];
    const float* in_nw   = (const float*)d_in[5];
    const float* q_w     = (const float*)d_in[6];
    const float* k_w     = (const float*)d_in[7];
    const float* v_w     = (const float*)d_in[8];
    const float* o_w     = (const float*)d_in[9];
    const float* post_nw = (const float*)d_in[10];
    const float* gate_w  = (const float*)d_in[11];
    const float* up_w    = (const float*)d_in[12];
    const float* down_w  = (const float*)d_in[13];
    float* out = (float*)d_out;

    float *cat, *x1, *h1, *qf, *kf, *vf, *vt, *sc, *ao, *x2, *h2, *gf, *uf;
    cudaGetSymbolAddress((void**)&cat, g_cat);
    cudaGetSymbolAddress((void**)&x1,  g_x1);
    cudaGetSymbolAddress((void**)&h1,  g_h1);
    cudaGetSymbolAddress((void**)&qf,  g_qf);
    cudaGetSymbolAddress((void**)&kf,  g_kf);
    cudaGetSymbolAddress((void**)&vf,  g_vf);
    cudaGetSymbolAddress((void**)&vt,  g_vt);
    cudaGetSymbolAddress((void**)&sc,  g_sc);
    cudaGetSymbolAddress((void**)&ao,  g_ao);
    cudaGetSymbolAddress((void**)&x2,  g_x2);
    cudaGetSymbolAddress((void**)&h2,  g_h2);
    cudaGetSymbolAddress((void**)&gf,  g_gf);
    cudaGetSymbolAddress((void**)&uf,  g_uf);

    const float scale = 0.08838834764831845f;  // 1/sqrt(128)

    // fc fusion
    concat_kernel<<<(S_LEN * H2_DIM) / 256, 256>>>(embeds, hidden, cat);
    run_gemm(cat, fc_w, x1, S_LEN, H_DIM, H2_DIM, H2_DIM, H2_DIM, H_DIM,
             1.f, fc_b, nullptr, 0, 0, 1, 0, 1, 0, 1);

    // attention block
    rmsnorm_kernel<<<S_LEN, 256>>>(x1, in_nw, h1);
    run_gemm(h1, q_w, qf, S_LEN, QDIM,  H_DIM, H_DIM, H_DIM, QDIM,
             1.f, nullptr, nullptr, 0, 0, 1, 0, 1, 0, 1);
    run_gemm(h1, k_w, kf, S_LEN, KVDIM, H_DIM, H_DIM, H_DIM, KVDIM,
             1.f, nullptr, nullptr, 0, 0, 1, 0, 1, 0, 1);
    run_gemm(h1, v_w, vf, S_LEN, KVDIM, H_DIM, H_DIM, H_DIM, KVDIM,
             1.f, nullptr, nullptr, 0, 0, 1, 0, 1, 0, 1);

    rope_kernel<<<(S_LEN * NHEADS * 64) / 256, 256>>>(qf, NHEADS);
    rope_kernel<<<(S_LEN * NKV * 64) / 256, 256>>>(kf, NKV);
    transpose_kernel<<<dim3(KVDIM / 32, S_LEN / 32), dim3(32, 8)>>>(vf, vt, S_LEN, KVDIM);

    // scores[h] = scale * Q_h K_h^T   (batched over 32 heads)
    run_gemm(qf, kf, sc, S_LEN, S_LEN, HEADD, QDIM, KVDIM, S_LEN,
             scale, nullptr, nullptr, 0,
             (long long)HEADD, 1, (long long)HEADD, 4,
             (long long)S_LEN * S_LEN, NHEADS);
    softmax_kernel<<<dim3(S_LEN, NHEADS), 256>>>(sc, amask);
    // out[h] = P_h V_h  -> [S, NH*D]
    run_gemm(sc, vt, ao, S_LEN, HEADD, S_LEN, S_LEN, S_LEN, QDIM,
             1.f, nullptr, nullptr, 0,
             (long long)S_LEN * S_LEN, 1, (long long)HEADD * S_LEN, 4,
             (long long)HEADD, NHEADS);

    // o-proj + residual
    run_gemm(ao, o_w, x2, S_LEN, H_DIM, QDIM, QDIM, QDIM, H_DIM,
             1.f, nullptr, x1, H_DIM, 0, 1, 0, 1, 0, 1);

    // MLP block
    rmsnorm_kernel<<<S_LEN, 256>>>(x2, post_nw, h2);
    run_gemm(h2, gate_w, gf, S_LEN, I_DIM, H_DIM, H_DIM, H_DIM, I_DIM,
             1.f, nullptr, nullptr, 0, 0, 1, 0, 1, 0, 1);
    run_gemm(h2, up_w, uf, S_LEN, I_DIM, H_DIM, H_DIM, H_DIM, I_DIM,
             1.f, nullptr, nullptr, 0, 0, 1, 0, 1, 0, 1);
    silu_mul_kernel<<<((size_t)S_LEN * I_DIM + 255) / 256, 256>>>(
        gf, uf, (size_t)S_LEN * I_DIM);
    run_gemm(gf, down_w, out, S_LEN, H_DIM, I_DIM, I_DIM, I_DIM, H_DIM,
             1.f, nullptr, x2, H_DIM, 0, 1, 0, 1, 0, 1);
}

// round 7
// speedup vs baseline: 1.1045x; 1.1045x over previous
#include <cuda_runtime.h>
#include <cuda_bf16.h>
#include <cstdint>
#include <cstdio>

// ---------------------------------------------------------------------------
// EAGLE draft layer forward, sm_103a. Round 5:
//  - all GEMM operands pre-rounded to tf32 in memory (weights converted once
//    per launch; activations rounded by their producer kernels)
//  - GEMM inner loop: cp.async.cg (3-stage) + ldmatrix + mma only
// ---------------------------------------------------------------------------

#define S_LEN 2048
#define H_DIM 4096
#define H2_DIM 8192
#define NHEADS 32
#define NKV 8
#define HEADD 128
#define KVDIM (NKV * HEADD)      // 1024
#define QDIM  (NHEADS * HEADD)   // 4096
#define I_DIM 11008

// ------------------------- static scratch (fp32) ---------------------------
__device__ float g_cat[(size_t)S_LEN * H2_DIM];
__device__ float g_x1 [(size_t)S_LEN * H_DIM];
__device__ float g_h1 [(size_t)S_LEN * H_DIM];
__device__ float g_qf [(size_t)S_LEN * QDIM];
__device__ float g_kf [(size_t)S_LEN * KVDIM];
__device__ float g_vf [(size_t)S_LEN * KVDIM];
__device__ float g_vt [(size_t)KVDIM * S_LEN];
__device__ float g_sc [(size_t)NHEADS * S_LEN * S_LEN];
__device__ float g_ao [(size_t)S_LEN * QDIM];
__device__ float g_x2 [(size_t)S_LEN * H_DIM];
__device__ float g_h2 [(size_t)S_LEN * H_DIM];
__device__ float g_gf [(size_t)S_LEN * I_DIM];
__device__ float g_uf [(size_t)S_LEN * I_DIM];

// tf32-rounded weight copies
__device__ float g_wfc[(size_t)H_DIM * H2_DIM];
__device__ float g_wq [(size_t)QDIM * H_DIM];
__device__ float g_wk [(size_t)KVDIM * H_DIM];
__device__ float g_wv [(size_t)KVDIM * H_DIM];
__device__ float g_wo [(size_t)H_DIM * QDIM];
__device__ float g_wg [(size_t)I_DIM * H_DIM];
__device__ float g_wu [(size_t)I_DIM * H_DIM];
__device__ float g_wd [(size_t)H_DIM * I_DIM];

__device__ __forceinline__ float f2tf_f(float x) {
    uint32_t r;
    asm("cvt.rna.tf32.f32 %0, %1;" : "=r"(r) : "f"(x));
    return __uint_as_float(r);
}

// --------------------------- elementwise kernels ---------------------------

__global__ void cvt_tf32_kernel(const float4* __restrict__ in,
                                float4* __restrict__ out, size_t n4) {
    size_t idx = (size_t)blockIdx.x * 256 + threadIdx.x;
    if (idx < n4) {
        float4 v = in[idx];
        v.x = f2tf_f(v.x); v.y = f2tf_f(v.y); v.z = f2tf_f(v.z); v.w = f2tf_f(v.w);
        out[idx] = v;
    }
}

__global__ void concat_kernel(const float* __restrict__ emb,
                              const float* __restrict__ hid,
                              float* __restrict__ cat) {
    int idx = blockIdx.x * 256 + threadIdx.x;
    int s = idx >> 13;
    int c = idx & 8191;
    float v = (c < H_DIM) ? emb[(size_t)s * H_DIM + c]
                          : hid[(size_t)s * H_DIM + (c - H_DIM)];
    cat[idx] = f2tf_f(v);
}

__global__ __launch_bounds__(256) void rmsnorm_kernel(const float* __restrict__ x,
                                                      const float* __restrict__ w,
                                                      float* __restrict__ out) {
    int row = blockIdx.x;
    const float* xr = x + (size_t)row * H_DIM;
    float s = 0.f;
    for (int i = threadIdx.x; i < H_DIM; i += 256) { float v = xr[i]; s += v * v; }
    __shared__ float red[256];
    red[threadIdx.x] = s; __syncthreads();
    #pragma unroll
    for (int k = 128; k > 0; k >>= 1) {
        if (threadIdx.x < k) red[threadIdx.x] += red[threadIdx.x + k];
        __syncthreads();
    }
    float scale = rsqrtf(red[0] / (float)H_DIM + 1e-6f);
    for (int i = threadIdx.x; i < H_DIM; i += 256)
        out[(size_t)row * H_DIM + i] = f2tf_f(xr[i] * scale * w[i]);
}

// In-place RoPE (pos = seq index); writes tf32-rounded values.
__global__ void rope_kernel(float* __restrict__ buf, int nheads) {
    int idx = blockIdx.x * 256 + threadIdx.x;
    int total = S_LEN * nheads * 64;
    if (idx >= total) return;
    int i    = idx & 63;
    int head = (idx >> 6) % nheads;
    int s    = idx / (nheads * 64);
    float pos = (float)s;
    float inv = expf(-(float)(2 * i) * (9.210340371976184f / 128.f));
    float ang = pos * inv;
    float c = cosf(ang), sn = sinf(ang);
    size_t base = (size_t)s * (nheads * HEADD) + (size_t)head * HEADD + i;
    float x1 = buf[base], x2 = buf[base + 64];
    buf[base]      = f2tf_f(x1 * c - x2 * sn);
    buf[base + 64] = f2tf_f(x2 * c + x1 * sn);
}

__global__ void transpose_kernel(const float* __restrict__ in,
                                 float* __restrict__ out, int rows, int cols) {
    __shared__ float tile[32][33];
    int c0 = blockIdx.x * 32, r0 = blockIdx.y * 32;
    int x = threadIdx.x, y = threadIdx.y;
    #pragma unroll
    for (int j = 0; j < 32; j += 8)
        tile[y + j][x] = in[(size_t)(r0 + y + j) * cols + (c0 + x)];
    __syncthreads();
    #pragma unroll
    for (int j = 0; j < 32; j += 8)
        out[(size_t)(c0 + y + j) * rows + (r0 + x)] = f2tf_f(tile[x][y + j]);
}

__global__ __launch_bounds__(256) void softmax_kernel(float* __restrict__ sc,
                                                      const float* __restrict__ amask) {
    int i = blockIdx.x;
    int h = blockIdx.y;
    float* row = sc + ((size_t)h * S_LEN + i) * S_LEN;
    int t = threadIdx.x;
    float v[8];
    float mx = -INFINITY;
    #pragma unroll
    for (int r = 0; r < 8; r++) {
        int j = t + r * 256;
        bool ok = (j <= i) && (amask[j] > 0.5f);
        float x = ok ? row[j] : -INFINITY;
        v[r] = x;
        mx = fmaxf(mx, x);
    }
    __shared__ float red[256];
    red[t] = mx; __syncthreads();
    #pragma unroll
    for (int k = 128; k > 0; k >>= 1) {
        if (t < k) red[t] = fmaxf(red[t], red[t + k]);
        __syncthreads();
    }
    mx = red[0]; __syncthreads();
    float sum = 0.f;
    #pragma unroll
    for (int r = 0; r < 8; r++) { float e = expf(v[r] - mx); v[r] = e; sum += e; }
    red[t] = sum; __syncthreads();
    #pragma unroll
    for (int k = 128; k > 0; k >>= 1) {
        if (t < k) red[t] += red[t + k];
        __syncthreads();
    }
    float invs = 1.f / red[0];
    #pragma unroll
    for (int r = 0; r < 8; r++) row[t + r * 256] = f2tf_f(v[r] * invs);
}

__global__ void silu_mul_kernel(float* __restrict__ g, const float* __restrict__ u,
                                size_t n) {
    size_t idx = (size_t)blockIdx.x * 256 + threadIdx.x;
    if (idx < n) {
        float x = g[idx];
        g[idx] = f2tf_f(x * (1.f / (1.f + expf(-x))) * u[idx]);
    }
}

// ----------------------------- TF32 NT GEMM --------------------------------
// C[M,N] = alpha * A[M,K] * B[N,K]^T (+ bias) (+ res) [optional tf32-round].
// Operands are pre-rounded tf32 bit patterns. BM=BN=128, BK=16, 8 warps,
// warp tile 64x32, m16n8k8 TF32 mma. 3-stage cp.async.cg pipeline,
// padded 20-word smem rows (conflict-free for ldmatrix pattern).

#define ROWW 20
#define STW (128 * ROWW)          // words per stage per matrix
#define STAGES 3
#define GEMM_SMEM (STAGES * STW * 2 * 4)   // 61440 bytes

__device__ __forceinline__ void cp16(uint32_t saddr, const float* gptr) {
    asm volatile("cp.async.cg.shared.global [%0], [%1], 16;"
                 :: "r"(saddr), "l"(__cvta_generic_to_global(gptr)));
}

__global__ __launch_bounds__(256) void gemm_tf32_nt(
    const float* __restrict__ A, const float* __restrict__ B, float* __restrict__ C,
    int M, int N, int K, int lda, int ldb, int ldc, float alpha,
    const float* __restrict__ bias, const float* __restrict__ res, int ldres,
    long long aStride, int aDiv, long long bStride, int bDiv, long long cStride,
    int roundOut)
{
    (void)M; (void)N;
    extern __shared__ __align__(16) uint32_t smem[];
    uint32_t* As = smem;
    uint32_t* Bs = smem + STAGES * STW;

    int z = blockIdx.z;
    A += (long long)(z / aDiv) * aStride;
    B += (long long)(z / bDiv) * bStride;
    C += (long long)z * cStride;

    int tid  = threadIdx.x;
    int warp = tid >> 5, lane = tid & 31;
    int wm = warp >> 2;       // 0..1
    int wn = warp & 3;        // 0..3
    int bm = blockIdx.y * 128, bn = blockIdx.x * 128;
    int g = lane >> 2, ctg = lane & 3;

    float acc[4][4][4] = {};

    // global load addressing: 16B per cp.async, 4 per thread per stage
    int lrow = tid >> 2;            // 0..63
    int lcol = (tid & 3) * 4;       // 0,4,8,12
    const float* Aptr = A + (size_t)(bm + lrow) * lda + lcol;
    const float* Bptr = B + (size_t)(bn + lrow) * ldb + lcol;

    uint32_t smA = (uint32_t)__cvta_generic_to_shared(As);
    uint32_t smB = (uint32_t)__cvta_generic_to_shared(Bs);
    uint32_t stByte = (uint32_t)(lrow * ROWW + lcol) * 4;

    // ldmatrix per-lane addresses (stage 0 base)
    uint32_t aAddr = smA + ((uint32_t)(wm * 64 + (lane & 15)) * (ROWW * 4))
                   + ((uint32_t)(lane >> 4) << 4);
    uint32_t bAddr = smB + ((uint32_t)(wn * 32 + (lane & 7) + ((lane >> 4) << 3)) * (ROWW * 4))
                   + ((uint32_t)((lane >> 3) & 1) << 4);

    int nIter = K >> 4;

    auto issue = [&](int it) {
        if (it < nIter) {
            int k0 = it << 4;
            uint32_t slotB = (uint32_t)(it % STAGES) * (STW * 4);
            uint32_t sA = smA + slotB + stByte;
            cp16(sA, Aptr + k0);
            cp16(sA + 64 * ROWW * 4, Aptr + (size_t)64 * lda + k0);
            uint32_t sB = smB + slotB + stByte;
            cp16(sB, Bptr + k0);
            cp16(sB + 64 * ROWW * 4, Bptr + (size_t)64 * ldb + k0);
        }
        asm volatile("cp.async.commit_group;" ::: "memory");
    };

    #pragma unroll
    for (int s = 0; s < STAGES - 1; s++) issue(s);

    for (int it = 0; it < nIter; it++) {
        asm volatile("cp.async.wait_group %0;" :: "n"(STAGES - 2) : "memory");
        __syncthreads();

        uint32_t slotB = (uint32_t)(it % STAGES) * (STW * 4);
        #pragma unroll
        for (int kk = 0; kk < 2; kk++) {
            uint32_t a[4][4], b[4][2];
            #pragma unroll
            for (int mt = 0; mt < 4; mt++) {
                uint32_t ad = aAddr + slotB + (uint32_t)(mt * 16 * ROWW * 4) + (uint32_t)(kk * 32);
                asm volatile("ldmatrix.sync.aligned.m8n8.x4.shared.b16 {%0,%1,%2,%3}, [%4];"
                             : "=r"(a[mt][0]), "=r"(a[mt][1]), "=r"(a[mt][2]), "=r"(a[mt][3])
                             : "r"(ad));
            }
            #pragma unroll
            for (int j = 0; j < 2; j++) {
                uint32_t bd = bAddr + slotB + (uint32_t)(j * 16 * ROWW * 4) + (uint32_t)(kk * 32);
                asm volatile("ldmatrix.sync.aligned.m8n8.x4.shared.b16 {%0,%1,%2,%3}, [%4];"
                             : "=r"(b[2*j][0]), "=r"(b[2*j][1]), "=r"(b[2*j+1][0]), "=r"(b[2*j+1][1])
                             : "r"(bd));
            }
            #pragma unroll
            for (int mt = 0; mt < 4; mt++)
                #pragma unroll
                for (int nt = 0; nt < 4; nt++)
                    asm volatile(
                        "mma.sync.aligned.m16n8k8.row.col.f32.tf32.tf32.f32 "
                        "{%0,%1,%2,%3}, {%4,%5,%6,%7}, {%8,%9}, {%0,%1,%2,%3};"
                        : "+f"(acc[mt][nt][0]), "+f"(acc[mt][nt][1]),
                          "+f"(acc[mt][nt][2]), "+f"(acc[mt][nt][3])
                        : "r"(a[mt][0]), "r"(a[mt][1]), "r"(a[mt][2]), "r"(a[mt][3]),
                          "r"(b[nt][0]), "r"(b[nt][1]));
        }

        issue(it + STAGES - 1);
    }

    // epilogue: float2 stores
    #pragma unroll
    for (int mt = 0; mt < 4; mt++) {
        int row0 = bm + wm * 64 + mt * 16 + g;
        #pragma unroll
        for (int nt = 0; nt < 4; nt++) {
            int col0 = bn + wn * 32 + nt * 8 + ctg * 2;
            #pragma unroll
            for (int half = 0; half < 2; half++) {
                int row = row0 + half * 8;
                float2 v;
                v.x = acc[mt][nt][half * 2 + 0] * alpha;
                v.y = acc[mt][nt][half * 2 + 1] * alpha;
                if (bias) { v.x += bias[col0]; v.y += bias[col0 + 1]; }
                if (res) {
                    const float2 r = *(const float2*)&res[(size_t)row * ldres + col0];
                    v.x += r.x; v.y += r.y;
                }
                if (roundOut) { v.x = f2tf_f(v.x); v.y = f2tf_f(v.y); }
                *(float2*)&C[(size_t)row * ldc + col0] = v;
            }
        }
    }
}

static inline void run_gemm(const float* A, const float* B, float* C,
                            int M, int N, int K, int lda, int ldb, int ldc,
                            float alpha, const float* bias,
                            const float* res, int ldres,
                            long long aStride, int aDiv,
                            long long bStride, int bDiv,
                            long long cStride, int batch, int roundOut) {
    dim3 grid(N / 128, M / 128, batch);
    gemm_tf32_nt<<<grid, 256, GEMM_SMEM>>>(A, B, C, M, N, K, lda, ldb, ldc, alpha,
                                           bias, res, ldres, aStride, aDiv,
                                           bStride, bDiv, cStride, roundOut);
}

// ------------------------------ orchestration ------------------------------

static inline void cvt_w(const float* in, float* out, size_t n) {
    size_t n4 = n / 4;
    cvt_tf32_kernel<<<(unsigned)((n4 + 255) / 256), 256>>>(
        (const float4*)in, (float4*)out, n4);
}

extern "C" void kernel_launch(void* const* d_in, const int* in_sizes, int n_in,
                              void* d_out, int out_size) {
    (void)in_sizes; (void)n_in; (void)out_size;
    const float* hidden  = (const float*)d_in[0];
    const float* embeds  = (const float*)d_in[1];
    const float* amask   = (const float*)d_in[2];
    const float* fc_w    = (const float*)d_in[3];
    const float* fc_b    = (const float*)d_in[4];
    const float* in_nw   = (const float*)d_in[5];
    const float* q_w     = (const float*)d_in[6];
    const float* k_w     = (const float*)d_in[7];
    const float* v_w     = (const float*)d_in[8];
    const float* o_w     = (const float*)d_in[9];
    const float* post_nw = (const float*)d_in[10];
    const float* gate_w  = (const float*)d_in[11];
    const float* up_w    = (const float*)d_in[12];
    const float* down_w  = (const float*)d_in[13];
    float* out = (float*)d_out;

    cudaFuncSetAttribute(gemm_tf32_nt,
                         cudaFuncAttributeMaxDynamicSharedMemorySize, GEMM_SMEM);

    float *cat, *x1, *h1, *qf, *kf, *vf, *vt, *sc, *ao, *x2, *h2, *gf, *uf;
    float *wfc, *wq, *wk, *wv, *wo, *wg, *wu, *wd;
    cudaGetSymbolAddress((void**)&cat, g_cat);
    cudaGetSymbolAddress((void**)&x1,  g_x1);
    cudaGetSymbolAddress((void**)&h1,  g_h1);
    cudaGetSymbolAddress((void**)&qf,  g_qf);
    cudaGetSymbolAddress((void**)&kf,  g_kf);
    cudaGetSymbolAddress((void**)&vf,  g_vf);
    cudaGetSymbolAddress((void**)&vt,  g_vt);
    cudaGetSymbolAddress((void**)&sc,  g_sc);
    cudaGetSymbolAddress((void**)&ao,  g_ao);
    cudaGetSymbolAddress((void**)&x2,  g_x2);
    cudaGetSymbolAddress((void**)&h2,  g_h2);
    cudaGetSymbolAddress((void**)&gf,  g_gf);
    cudaGetSymbolAddress((void**)&uf,  g_uf);
    cudaGetSymbolAddress((void**)&wfc, g_wfc);
    cudaGetSymbolAddress((void**)&wq,  g_wq);
    cudaGetSymbolAddress((void**)&wk,  g_wk);
    cudaGetSymbolAddress((void**)&wv,  g_wv);
    cudaGetSymbolAddress((void**)&wo,  g_wo);
    cudaGetSymbolAddress((void**)&wg,  g_wg);
    cudaGetSymbolAddress((void**)&wu,  g_wu);
    cudaGetSymbolAddress((void**)&wd,  g_wd);

    // weight rounding (once per launch)
    cvt_w(fc_w,   wfc, (size_t)H_DIM * H2_DIM);
    cvt_w(q_w,    wq,  (size_t)QDIM * H_DIM);
    cvt_w(k_w,    wk,  (size_t)KVDIM * H_DIM);
    cvt_w(v_w,    wv,  (size_t)KVDIM * H_DIM);
    cvt_w(o_w,    wo,  (size_t)H_DIM * QDIM);
    cvt_w(gate_w, wg,  (size_t)I_DIM * H_DIM);
    cvt_w(up_w,   wu,  (size_t)I_DIM * H_DIM);
    cvt_w(down_w, wd,  (size_t)H_DIM * I_DIM);

    const float scale = 0.08838834764831845f;  // 1/sqrt(128)

    // fc fusion
    concat_kernel<<<(S_LEN * H2_DIM) / 256, 256>>>(embeds, hidden, cat);
    run_gemm(cat, wfc, x1, S_LEN, H_DIM, H2_DIM, H2_DIM, H2_DIM, H_DIM,
             1.f, fc_b, nullptr, 0, 0, 1, 0, 1, 0, 1, 0);

    // attention block
    rmsnorm_kernel<<<S_LEN, 256>>>(x1, in_nw, h1);
    run_gemm(h1, wq, qf, S_LEN, QDIM,  H_DIM, H_DIM, H_DIM, QDIM,
             1.f, nullptr, nullptr, 0, 0, 1, 0, 1, 0, 1, 0);
    run_gemm(h1, wk, kf, S_LEN, KVDIM, H_DIM, H_DIM, H_DIM, KVDIM,
             1.f, nullptr, nullptr, 0, 0, 1, 0, 1, 0, 1, 0);
    run_gemm(h1, wv, vf, S_LEN, KVDIM, H_DIM, H_DIM, H_DIM, KVDIM,
             1.f, nullptr, nullptr, 0, 0, 1, 0, 1, 0, 1, 0);

    rope_kernel<<<(S_LEN * NHEADS * 64) / 256, 256>>>(qf, NHEADS);
    rope_kernel<<<(S_LEN * NKV * 64) / 256, 256>>>(kf, NKV);
    transpose_kernel<<<dim3(KVDIM / 32, S_LEN / 32), dim3(32, 8)>>>(vf, vt, S_LEN, KVDIM);

    // scores[h] = scale * Q_h K_h^T   (batched over 32 heads)
    run_gemm(qf, kf, sc, S_LEN, S_LEN, HEADD, QDIM, KVDIM, S_LEN,
             scale, nullptr, nullptr, 0,
             (long long)HEADD, 1, (long long)HEADD, 4,
             (long long)S_LEN * S_LEN, NHEADS, 0);
    softmax_kernel<<<dim3(S_LEN, NHEADS), 256>>>(sc, amask);
    // out[h] = P_h V_h  -> [S, NH*D]; round output (feeds o-proj GEMM)
    run_gemm(sc, vt, ao, S_LEN, HEADD, S_LEN, S_LEN, S_LEN, QDIM,
             1.f, nullptr, nullptr, 0,
             (long long)S_LEN * S_LEN, 1, (long long)HEADD * S_LEN, 4,
             (long long)HEADD, NHEADS, 1);

    // o-proj + residual
    run_gemm(ao, wo, x2, S_LEN, H_DIM, QDIM, QDIM, QDIM, H_DIM,
             1.f, nullptr, x1, H_DIM, 0, 1, 0, 1, 0, 1, 0);

    // MLP block
    rmsnorm_kernel<<<S_LEN, 256>>>(x2, post_nw, h2);
    run_gemm(h2, wg, gf, S_LEN, I_DIM, H_DIM, H_DIM, H_DIM, I_DIM,
             1.f, nullptr, nullptr, 0, 0, 1, 0, 1, 0, 1, 0);
    run_gemm(h2, wu, uf, S_LEN, I_DIM, H_DIM, H_DIM, H_DIM, I_DIM,
             1.f, nullptr, nullptr, 0, 0, 1, 0, 1, 0, 1, 0);
    silu_mul_kernel<<<((size_t)S_LEN * I_DIM + 255) / 256, 256>>>(
        gf, uf, (size_t)S_LEN * I_DIM);
    run_gemm(gf, wd, out, S_LEN, H_DIM, I_DIM, I_DIM, I_DIM, H_DIM,
             1.f, nullptr, x2, H_DIM, 0, 1, 0, 1, 0, 1, 0);
}